// round 1
// baseline (speedup 1.0000x reference)
#include <cuda_runtime.h>

#define B_   4
#define SX_  4096
#define SL_  256
#define D_   1024
#define H_   16
#define DH_  64
#define SKV_ (SX_ + SL_)   // 4352

// ---------------- scratch (device globals, no allocation) ----------------
__device__ float g_kvin[(size_t)B_ * SKV_ * D_];        //  71 MB: concat(LN(x), LN(latents))
__device__ float g_ln  [(size_t)B_ * SL_  * D_];        //   4 MB: LN(latents)
__device__ float g_q   [(size_t)B_ * SL_  * D_];        //   4 MB
__device__ float g_kv  [(size_t)B_ * SKV_ * 2 * D_];    // 143 MB: [k | v]
__device__ float g_kT  [(size_t)B_ * H_ * DH_ * SKV_];  //  71 MB: k transposed per head
__device__ float g_s   [(size_t)B_ * H_ * SL_ * SKV_];  // 285 MB: scores / probs
__device__ float g_y   [(size_t)B_ * SL_  * D_];        //   4 MB

// ---------------- LayerNorm: one block per row (D=1024) ----------------
__global__ __launch_bounds__(256) void ln_kernel(
    const float* __restrict__ x, const float* __restrict__ g,
    const float* __restrict__ bta, float* __restrict__ dst1,
    float* __restrict__ dst2, int rowsPerBatch, int rowOff)
{
    int r = blockIdx.x;
    int tid = threadIdx.x;
    const float* xr = x + (size_t)r * D_;

    float v[4], s = 0.f, s2 = 0.f;
#pragma unroll
    for (int i = 0; i < 4; i++) {
        v[i] = xr[tid + i * 256];
        s += v[i];
        s2 += v[i] * v[i];
    }
#pragma unroll
    for (int o = 16; o > 0; o >>= 1) {
        s  += __shfl_xor_sync(0xffffffffu, s,  o);
        s2 += __shfl_xor_sync(0xffffffffu, s2, o);
    }
    __shared__ float ss[8], ss2[8];
    int w = tid >> 5, l = tid & 31;
    if (l == 0) { ss[w] = s; ss2[w] = s2; }
    __syncthreads();
    if (tid == 0) {
        float a = 0.f, b2 = 0.f;
#pragma unroll
        for (int i = 0; i < 8; i++) { a += ss[i]; b2 += ss2[i]; }
        float mu = a * (1.f / D_);
        ss[0]  = mu;
        ss2[0] = b2 * (1.f / D_) - mu * mu;
    }
    __syncthreads();
    float mu = ss[0];
    float inv = rsqrtf(ss2[0] + 1e-5f);

    size_t drow = ((size_t)(r / rowsPerBatch) * SKV_ + (r % rowsPerBatch) + rowOff) * D_;
#pragma unroll
    for (int i = 0; i < 4; i++) {
        int c = tid + i * 256;
        float o = (v[i] - mu) * inv * g[c] + bta[c];
        dst1[drow + c] = o;
        if (dst2) dst2[(size_t)r * D_ + c] = o;
    }
}

// ---------------- generic batched SGEMM, 64x64 tile, K-tile 16 ----------------
// C[m][n] = sum_k A[m][k] * B[k][n]; all dims multiples of 64 (M,N) / 16 (K).
// blockIdx.z = b*Hdim + h; per-operand batch/head strides.
__global__ __launch_bounds__(256) void sgemm64(
    const float* __restrict__ A, int lda, long long sAb, long long sAh,
    const float* __restrict__ Bm, int ldb, long long sBb, long long sBh,
    float* __restrict__ C, int ldc, long long sCb, long long sCh,
    int K, int Hdim)
{
    int z = blockIdx.z;
    int bb = z / Hdim, hh = z % Hdim;
    A  += (size_t)bb * sAb + (size_t)hh * sAh;
    Bm += (size_t)bb * sBb + (size_t)hh * sBh;
    C  += (size_t)bb * sCb + (size_t)hh * sCh;

    int row0 = blockIdx.y * 64, col0 = blockIdx.x * 64;

    __shared__ float As[16][64];
    __shared__ float Bs[16][64];

    int tid = threadIdx.y * 16 + threadIdx.x;
    int am = tid >> 2;              // 0..63
    int ak = (tid & 3) * 4;         // 0,4,8,12
    int bk = tid >> 4;              // 0..15
    int bn = (tid & 15) * 4;        // 0..60

    const float* Aptr = A  + (size_t)(row0 + am) * lda + ak;
    const float* Bptr = Bm + (size_t)bk * ldb + col0 + bn;

    int ty4 = threadIdx.y * 4, tx4 = threadIdx.x * 4;
    float c[4][4] = {};

    for (int k0 = 0; k0 < K; k0 += 16) {
        float4 av = *(const float4*)Aptr;
        float4 bv = *(const float4*)Bptr;
        As[ak + 0][am] = av.x;
        As[ak + 1][am] = av.y;
        As[ak + 2][am] = av.z;
        As[ak + 3][am] = av.w;
        *(float4*)&Bs[bk][bn] = bv;
        __syncthreads();
#pragma unroll
        for (int kk = 0; kk < 16; kk++) {
            float4 a = *(const float4*)&As[kk][ty4];
            float4 b = *(const float4*)&Bs[kk][tx4];
            c[0][0] += a.x * b.x; c[0][1] += a.x * b.y; c[0][2] += a.x * b.z; c[0][3] += a.x * b.w;
            c[1][0] += a.y * b.x; c[1][1] += a.y * b.y; c[1][2] += a.y * b.z; c[1][3] += a.y * b.w;
            c[2][0] += a.z * b.x; c[2][1] += a.z * b.y; c[2][2] += a.z * b.z; c[2][3] += a.z * b.w;
            c[3][0] += a.w * b.x; c[3][1] += a.w * b.y; c[3][2] += a.w * b.z; c[3][3] += a.w * b.w;
        }
        __syncthreads();
        Aptr += 16;
        Bptr += (size_t)16 * ldb;
    }

#pragma unroll
    for (int i = 0; i < 4; i++) {
        float4 o = make_float4(c[i][0], c[i][1], c[i][2], c[i][3]);
        *(float4*)&C[(size_t)(row0 + ty4 + i) * ldc + col0 + tx4] = o;
    }
}

// ---------------- per-head RMSNorm (warp per 64-wide chunk) ----------------
__global__ __launch_bounds__(256) void rms_kernel(
    float* __restrict__ p, const float* __restrict__ gamma,
    int rowStride, long long totalChunks)
{
    long long chunk = (long long)blockIdx.x * 8 + (threadIdx.x >> 5);
    if (chunk >= totalChunks) return;
    int lane = threadIdx.x & 31;
    long long row = chunk / H_;
    int h = (int)(chunk % H_);
    float* base = p + row * (size_t)rowStride + h * DH_;

    float v0 = base[lane];
    float v1 = base[lane + 32];
    float ss = v0 * v0 + v1 * v1;
#pragma unroll
    for (int o = 16; o > 0; o >>= 1) ss += __shfl_xor_sync(0xffffffffu, ss, o);
    float norm = sqrtf(ss) * 0.125f;           // * DH^-0.5
    float scale = 1.f / fmaxf(norm, 1e-8f);
    base[lane]      = v0 * scale * gamma[lane];
    base[lane + 32] = v1 * scale * gamma[lane + 32];
}

// ---------------- pack k -> kT[b][h][d][t] (coalesced transpose) ----------------
__global__ __launch_bounds__(256) void packKT(
    const float* __restrict__ kv, float* __restrict__ kT)
{
    int z = blockIdx.z;
    int b = z / H_, h = z % H_;
    __shared__ float tile[32][33];
    int t0 = blockIdx.x * 32, d0 = blockIdx.y * 32;
    int tx = threadIdx.x, ty = threadIdx.y;
#pragma unroll
    for (int j = 0; j < 4; j++) {
        int t = t0 + ty + j * 8;
        tile[ty + j * 8][tx] = kv[((size_t)b * SKV_ + t) * (2 * D_) + h * DH_ + d0 + tx];
    }
    __syncthreads();
#pragma unroll
    for (int j = 0; j < 4; j++) {
        int d = d0 + ty + j * 8;
        kT[(((size_t)b * H_ + h) * DH_ + d) * SKV_ + t0 + tx] = tile[tx][ty + j * 8];
    }
}

// ---------------- masked softmax over score rows ----------------
__global__ __launch_bounds__(256) void softmax_kernel(
    float* __restrict__ S, const float* __restrict__ mask_x,
    const float* __restrict__ mask_l)
{
    int q = blockIdx.x, h = blockIdx.y, b = blockIdx.z;
    float* row = S + (((size_t)b * H_ + h) * SL_ + q) * SKV_;
    float mlq = mask_l[b * SL_ + q];
    int tid = threadIdx.x;
    const float NEGMIN = -3.4028234663852886e38f;

    float lv[17];
    float mx = -3.4e38f;
#pragma unroll
    for (int i = 0; i < 17; i++) {
        int t = tid + i * 256;
        float km = (t < SX_) ? mask_x[b * SX_ + t] : mask_l[b * SL_ + (t - SX_)];
        float m = km * mlq;
        float sv = row[t] * 0.125f + (1.0f - m) * NEGMIN;
        lv[i] = sv;
        mx = fmaxf(mx, sv);
    }
    // block max
    __shared__ float red[8];
#pragma unroll
    for (int o = 16; o > 0; o >>= 1) mx = fmaxf(mx, __shfl_xor_sync(0xffffffffu, mx, o));
    int w = tid >> 5, l = tid & 31;
    if (l == 0) red[w] = mx;
    __syncthreads();
    if (tid == 0) {
        float a = red[0];
#pragma unroll
        for (int i = 1; i < 8; i++) a = fmaxf(a, red[i]);
        red[0] = a;
    }
    __syncthreads();
    mx = red[0];
    __syncthreads();

    float sum = 0.f;
#pragma unroll
    for (int i = 0; i < 17; i++) {
        float e = expf(lv[i] - mx);
        lv[i] = e;
        sum += e;
    }
#pragma unroll
    for (int o = 16; o > 0; o >>= 1) sum += __shfl_xor_sync(0xffffffffu, sum, o);
    if (l == 0) red[w] = sum;
    __syncthreads();
    if (tid == 0) {
        float a = 0.f;
#pragma unroll
        for (int i = 0; i < 8; i++) a += red[i];
        red[0] = a;
    }
    __syncthreads();
    float inv = 1.f / red[0];
#pragma unroll
    for (int i = 0; i < 17; i++) row[tid + i * 256] = lv[i] * inv;
}

// ---------------- launch ----------------
extern "C" void kernel_launch(void* const* d_in, const int* in_sizes, int n_in,
                              void* d_out, int out_size)
{
    const float* x       = (const float*)d_in[0];
    const float* latents = (const float*)d_in[1];
    const float* mask_x  = (const float*)d_in[2];
    const float* mask_l  = (const float*)d_in[3];
    const float* ln_x_g  = (const float*)d_in[4];
    const float* ln_x_b  = (const float*)d_in[5];
    const float* ln_l_g  = (const float*)d_in[6];
    const float* ln_l_b  = (const float*)d_in[7];
    const float* Wq      = (const float*)d_in[8];
    const float* Wkv     = (const float*)d_in[9];
    const float* qk_g    = (const float*)d_in[10];
    const float* Wo      = (const float*)d_in[11];
    float* out = (float*)d_out;

    float *kvin, *lnb, *qb, *kvb, *kT, *sb, *yb;
    cudaGetSymbolAddress((void**)&kvin, g_kvin);
    cudaGetSymbolAddress((void**)&lnb,  g_ln);
    cudaGetSymbolAddress((void**)&qb,   g_q);
    cudaGetSymbolAddress((void**)&kvb,  g_kv);
    cudaGetSymbolAddress((void**)&kT,   g_kT);
    cudaGetSymbolAddress((void**)&sb,   g_s);
    cudaGetSymbolAddress((void**)&yb,   g_y);

    dim3 t16(16, 16);

    // 1) LayerNorm(x) -> kvin rows [0,SX); LayerNorm(latents) -> kvin rows [SX,Skv) + lnbuf
    ln_kernel<<<B_ * SX_, 256>>>(x, ln_x_g, ln_x_b, kvin, nullptr, SX_, 0);
    ln_kernel<<<B_ * SL_, 256>>>(latents, ln_l_g, ln_l_b, kvin, lnb, SL_, SX_);

    // 2) q = ln @ Wq   [1024 x 1024 x 1024]
    sgemm64<<<dim3(D_ / 64, (B_ * SL_) / 64, 1), t16>>>(
        lnb, D_, 0, 0, Wq, D_, 0, 0, qb, D_, 0, 0, D_, 1);

    // 3) kv = kvin @ Wkv   [17408 x 2048 x 1024]
    sgemm64<<<dim3((2 * D_) / 64, (B_ * SKV_) / 64, 1), t16>>>(
        kvin, D_, 0, 0, Wkv, 2 * D_, 0, 0, kvb, 2 * D_, 0, 0, D_, 1);

    // 4) RMSNorm q and k (per 64-wide head chunk)
    rms_kernel<<<(B_ * SL_ * H_) / 8, 256>>>(qb, qk_g, D_, (long long)B_ * SL_ * H_);
    rms_kernel<<<(B_ * SKV_ * H_) / 8, 256>>>(kvb, qk_g, 2 * D_, (long long)B_ * SKV_ * H_);

    // 5) pack kT[b][h][d][t]
    packKT<<<dim3(SKV_ / 32, DH_ / 32, B_ * H_), dim3(32, 8)>>>(kvb, kT);

    // 6) scores = q @ kT   per (b,h): [256 x 4352 x 64]
    sgemm64<<<dim3(SKV_ / 64, SL_ / 64, B_ * H_), t16>>>(
        qb, D_, (long long)SL_ * D_, DH_,
        kT, SKV_, (long long)H_ * DH_ * SKV_, (long long)DH_ * SKV_,
        sb, SKV_, (long long)H_ * SL_ * SKV_, (long long)SL_ * SKV_,
        DH_, H_);

    // 7) softmax (scale + mask inside)
    softmax_kernel<<<dim3(SL_, H_, B_), 256>>>(sb, mask_x, mask_l);

    // 8) y = P @ V   per (b,h): [256 x 64 x 4352]
    sgemm64<<<dim3(DH_ / 64, SL_ / 64, B_ * H_), t16>>>(
        sb, SKV_, (long long)H_ * SL_ * SKV_, (long long)SL_ * SKV_,
        kvb + D_, 2 * D_, (long long)SKV_ * 2 * D_, DH_,
        yb, D_, (long long)SL_ * D_, DH_,
        SKV_, H_);

    // 9) out = y @ Wo   [1024 x 1024 x 1024]
    sgemm64<<<dim3(D_ / 64, (B_ * SL_) / 64, 1), t16>>>(
        yb, D_, 0, 0, Wo, D_, 0, 0, out, D_, 0, 0, D_, 1);
}

// round 2
// speedup vs baseline: 1.0114x; 1.0114x over previous
#include <cuda_runtime.h>

#define B_   4
#define SX_  4096
#define SL_  256
#define D_   1024
#define H_   16
#define DH_  64
#define SKV_ (SX_ + SL_)   // 4352

// ---------------- scratch (device globals, no allocation) ----------------
__device__ float g_kvin[(size_t)B_ * SKV_ * D_];        //  71 MB
__device__ float g_ln  [(size_t)B_ * SL_  * D_];        //   4 MB
__device__ float g_q   [(size_t)B_ * SL_  * D_];        //   4 MB
__device__ float g_kv  [(size_t)B_ * SKV_ * 2 * D_];    // 143 MB
__device__ float g_kT  [(size_t)B_ * H_ * DH_ * SKV_];  //  71 MB
__device__ float g_s   [(size_t)B_ * H_ * SL_ * SKV_];  // 285 MB
__device__ float g_y   [(size_t)B_ * SL_  * D_];        //   4 MB

// ---------------- LayerNorm: one block per row (D=1024) ----------------
__global__ __launch_bounds__(256) void ln_kernel(
    const float* __restrict__ x, const float* __restrict__ g,
    const float* __restrict__ bta, float* __restrict__ dst1,
    float* __restrict__ dst2, int rowsPerBatch, int rowOff)
{
    int r = blockIdx.x;
    int tid = threadIdx.x;
    const float* xr = x + (size_t)r * D_;

    float v[4], s = 0.f, s2 = 0.f;
#pragma unroll
    for (int i = 0; i < 4; i++) {
        v[i] = xr[tid + i * 256];
        s += v[i];
        s2 += v[i] * v[i];
    }
#pragma unroll
    for (int o = 16; o > 0; o >>= 1) {
        s  += __shfl_xor_sync(0xffffffffu, s,  o);
        s2 += __shfl_xor_sync(0xffffffffu, s2, o);
    }
    __shared__ float ss[8], ss2[8];
    int w = tid >> 5, l = tid & 31;
    if (l == 0) { ss[w] = s; ss2[w] = s2; }
    __syncthreads();
    if (tid == 0) {
        float a = 0.f, b2 = 0.f;
#pragma unroll
        for (int i = 0; i < 8; i++) { a += ss[i]; b2 += ss2[i]; }
        float mu = a * (1.f / D_);
        ss[0]  = mu;
        ss2[0] = b2 * (1.f / D_) - mu * mu;
    }
    __syncthreads();
    float mu = ss[0];
    float inv = rsqrtf(ss2[0] + 1e-5f);

    size_t drow = ((size_t)(r / rowsPerBatch) * SKV_ + (r % rowsPerBatch) + rowOff) * D_;
#pragma unroll
    for (int i = 0; i < 4; i++) {
        int c = tid + i * 256;
        float o = (v[i] - mu) * inv * g[c] + bta[c];
        dst1[drow + c] = o;
        if (dst2) dst2[(size_t)r * D_ + c] = o;
    }
}

// ---------------- batched SGEMM: 128 x TN tile, K-tile 8, 8x(TN/16) microtile ----
// C[m][n] = sum_k A[m][k]*B[k][n]. M multiple of 128, N multiple of TN, K of 8.
// Double-buffered smem, register prefetch, one sync per K-tile.
template<int TN>
__global__ __launch_bounds__(256) void sgemm128(
    const float* __restrict__ A, int lda, long long sAb, long long sAh,
    const float* __restrict__ Bm, int ldb, long long sBb, long long sBh,
    float* __restrict__ C, int ldc, long long sCb, long long sCh,
    int K, int Hdim)
{
    int z = blockIdx.z;
    int bb = z / Hdim, hh = z % Hdim;
    A  += (size_t)bb * sAb + (size_t)hh * sAh;
    Bm += (size_t)bb * sBb + (size_t)hh * sBh;
    C  += (size_t)bb * sCb + (size_t)hh * sCh;

    constexpr int TK = 8;
    constexpr int NC = (TN == 128) ? 8 : 4;   // cols per thread
    int row0 = blockIdx.y * 128, col0 = blockIdx.x * TN;

    __shared__ float As[2][TK][132];          // [k][m], padded
    __shared__ float Bs[2][TK][TN];           // [k][n]

    int tid = threadIdx.x;
    int tx = tid & 15, ty = tid >> 4;
    int tx4 = tx * 4, ty4 = ty * 4;

    // A global load: one float4/thread: row = tid>>1, k = (tid&1)*4
    int am = tid >> 1, ak = (tid & 1) * 4;
    const float* Aptr = A + (size_t)(row0 + am) * lda + ak;

    // B global load
    int bkr, bnc;
    bool bact;
    if (TN == 128) { bkr = tid >> 5; bnc = (tid & 31) * 4; bact = true; }
    else           { bkr = tid >> 4; bnc = (tid & 15) * 4; bact = (tid < 128); }
    const float* Bptr = Bm + (size_t)bkr * ldb + col0 + bnc;

    float4 apf = *(const float4*)Aptr;
    float4 bpf = make_float4(0.f, 0.f, 0.f, 0.f);
    if (bact) bpf = *(const float4*)Bptr;

    float acc[8][NC];
#pragma unroll
    for (int i = 0; i < 8; i++)
#pragma unroll
        for (int j = 0; j < NC; j++) acc[i][j] = 0.f;

    int buf = 0;
    for (int k0 = 0; k0 < K; k0 += TK) {
        As[buf][ak + 0][am] = apf.x;
        As[buf][ak + 1][am] = apf.y;
        As[buf][ak + 2][am] = apf.z;
        As[buf][ak + 3][am] = apf.w;
        if (bact) *(float4*)&Bs[buf][bkr][bnc] = bpf;
        __syncthreads();

        if (k0 + TK < K) {
            Aptr += TK;
            apf = *(const float4*)Aptr;
            Bptr += (size_t)TK * ldb;
            if (bact) bpf = *(const float4*)Bptr;
        }

#pragma unroll
        for (int kk = 0; kk < TK; kk++) {
            float a[8], b[NC];
            *(float4*)&a[0] = *(const float4*)&As[buf][kk][ty4];
            *(float4*)&a[4] = *(const float4*)&As[buf][kk][ty4 + 64];
            *(float4*)&b[0] = *(const float4*)&Bs[buf][kk][tx4];
            if (TN == 128)
                *(float4*)&b[4] = *(const float4*)&Bs[buf][kk][tx4 + 64];
#pragma unroll
            for (int i = 0; i < 8; i++)
#pragma unroll
                for (int j = 0; j < NC; j++)
                    acc[i][j] += a[i] * b[j];
        }
        buf ^= 1;
    }

#pragma unroll
    for (int i = 0; i < 4; i++) {
        size_t r1 = (size_t)(row0 + ty4 + i) * ldc + col0;
        size_t r2 = (size_t)(row0 + 64 + ty4 + i) * ldc + col0;
        *(float4*)&C[r1 + tx4] = make_float4(acc[i][0], acc[i][1], acc[i][2], acc[i][3]);
        *(float4*)&C[r2 + tx4] = make_float4(acc[i + 4][0], acc[i + 4][1], acc[i + 4][2], acc[i + 4][3]);
        if (TN == 128) {
            *(float4*)&C[r1 + tx4 + 64] = make_float4(acc[i][4], acc[i][5], acc[i][6], acc[i][7]);
            *(float4*)&C[r2 + tx4 + 64] = make_float4(acc[i + 4][4], acc[i + 4][5], acc[i + 4][6], acc[i + 4][7]);
        }
    }
}

// ---------------- per-head RMSNorm (warp per 64-wide chunk) ----------------
__global__ __launch_bounds__(256) void rms_kernel(
    float* __restrict__ p, const float* __restrict__ gamma,
    int rowStride, long long totalChunks)
{
    long long chunk = (long long)blockIdx.x * 8 + (threadIdx.x >> 5);
    if (chunk >= totalChunks) return;
    int lane = threadIdx.x & 31;
    long long row = chunk / H_;
    int h = (int)(chunk % H_);
    float* base = p + row * (size_t)rowStride + h * DH_;

    float v0 = base[lane];
    float v1 = base[lane + 32];
    float ss = v0 * v0 + v1 * v1;
#pragma unroll
    for (int o = 16; o > 0; o >>= 1) ss += __shfl_xor_sync(0xffffffffu, ss, o);
    float norm = sqrtf(ss) * 0.125f;
    float scale = 1.f / fmaxf(norm, 1e-8f);
    base[lane]      = v0 * scale * gamma[lane];
    base[lane + 32] = v1 * scale * gamma[lane + 32];
}

// ---------------- pack k -> kT[b][h][d][t] ----------------
__global__ __launch_bounds__(256) void packKT(
    const float* __restrict__ kv, float* __restrict__ kT)
{
    int z = blockIdx.z;
    int b = z / H_, h = z % H_;
    __shared__ float tile[32][33];
    int t0 = blockIdx.x * 32, d0 = blockIdx.y * 32;
    int tx = threadIdx.x, ty = threadIdx.y;
#pragma unroll
    for (int j = 0; j < 4; j++) {
        int t = t0 + ty + j * 8;
        tile[ty + j * 8][tx] = kv[((size_t)b * SKV_ + t) * (2 * D_) + h * DH_ + d0 + tx];
    }
    __syncthreads();
#pragma unroll
    for (int j = 0; j < 4; j++) {
        int d = d0 + ty + j * 8;
        kT[(((size_t)b * H_ + h) * DH_ + d) * SKV_ + t0 + tx] = tile[tx][ty + j * 8];
    }
}

// ---------------- masked softmax over score rows ----------------
__global__ __launch_bounds__(256) void softmax_kernel(
    float* __restrict__ S, const float* __restrict__ mask_x,
    const float* __restrict__ mask_l)
{
    int q = blockIdx.x, h = blockIdx.y, b = blockIdx.z;
    float* row = S + (((size_t)b * H_ + h) * SL_ + q) * SKV_;
    float mlq = mask_l[b * SL_ + q];
    int tid = threadIdx.x;
    const float NEGMIN = -3.4028234663852886e38f;

    float lv[17];
    float mx = -3.4e38f;
#pragma unroll
    for (int i = 0; i < 17; i++) {
        int t = tid + i * 256;
        float km = (t < SX_) ? mask_x[b * SX_ + t] : mask_l[b * SL_ + (t - SX_)];
        float m = km * mlq;
        float sv = row[t] * 0.125f + (1.0f - m) * NEGMIN;
        lv[i] = sv;
        mx = fmaxf(mx, sv);
    }
    __shared__ float red[8];
#pragma unroll
    for (int o = 16; o > 0; o >>= 1) mx = fmaxf(mx, __shfl_xor_sync(0xffffffffu, mx, o));
    int w = tid >> 5, l = tid & 31;
    if (l == 0) red[w] = mx;
    __syncthreads();
    if (tid == 0) {
        float a = red[0];
#pragma unroll
        for (int i = 1; i < 8; i++) a = fmaxf(a, red[i]);
        red[0] = a;
    }
    __syncthreads();
    mx = red[0];
    __syncthreads();

    float sum = 0.f;
#pragma unroll
    for (int i = 0; i < 17; i++) {
        float e = expf(lv[i] - mx);
        lv[i] = e;
        sum += e;
    }
#pragma unroll
    for (int o = 16; o > 0; o >>= 1) sum += __shfl_xor_sync(0xffffffffu, sum, o);
    if (l == 0) red[w] = sum;
    __syncthreads();
    if (tid == 0) {
        float a = 0.f;
#pragma unroll
        for (int i = 0; i < 8; i++) a += red[i];
        red[0] = a;
    }
    __syncthreads();
    float inv = 1.f / red[0];
#pragma unroll
    for (int i = 0; i < 17; i++) row[tid + i * 256] = lv[i] * inv;
}

// ---------------- launch ----------------
extern "C" void kernel_launch(void* const* d_in, const int* in_sizes, int n_in,
                              void* d_out, int out_size)
{
    const float* x       = (const float*)d_in[0];
    const float* latents = (const float*)d_in[1];
    const float* mask_x  = (const float*)d_in[2];
    const float* mask_l  = (const float*)d_in[3];
    const float* ln_x_g  = (const float*)d_in[4];
    const float* ln_x_b  = (const float*)d_in[5];
    const float* ln_l_g  = (const float*)d_in[6];
    const float* ln_l_b  = (const float*)d_in[7];
    const float* Wq      = (const float*)d_in[8];
    const float* Wkv     = (const float*)d_in[9];
    const float* qk_g    = (const float*)d_in[10];
    const float* Wo      = (const float*)d_in[11];
    float* out = (float*)d_out;

    float *kvin, *lnb, *qb, *kvb, *kT, *sb, *yb;
    cudaGetSymbolAddress((void**)&kvin, g_kvin);
    cudaGetSymbolAddress((void**)&lnb,  g_ln);
    cudaGetSymbolAddress((void**)&qb,   g_q);
    cudaGetSymbolAddress((void**)&kvb,  g_kv);
    cudaGetSymbolAddress((void**)&kT,   g_kT);
    cudaGetSymbolAddress((void**)&sb,   g_s);
    cudaGetSymbolAddress((void**)&yb,   g_y);

    // 1) LayerNorms -> kvin (concat) and lnb
    ln_kernel<<<B_ * SX_, 256>>>(x, ln_x_g, ln_x_b, kvin, nullptr, SX_, 0);
    ln_kernel<<<B_ * SL_, 256>>>(latents, ln_l_g, ln_l_b, kvin, lnb, SL_, SX_);

    // 2) q = ln @ Wq   [1024 x 1024 x 1024]
    sgemm128<128><<<dim3(D_ / 128, (B_ * SL_) / 128, 1), 256>>>(
        lnb, D_, 0, 0, Wq, D_, 0, 0, qb, D_, 0, 0, D_, 1);

    // 3) kv = kvin @ Wkv   [17408 x 2048 x 1024]
    sgemm128<128><<<dim3((2 * D_) / 128, (B_ * SKV_) / 128, 1), 256>>>(
        kvin, D_, 0, 0, Wkv, 2 * D_, 0, 0, kvb, 2 * D_, 0, 0, D_, 1);

    // 4) RMSNorm q and k
    rms_kernel<<<(B_ * SL_ * H_) / 8, 256>>>(qb, qk_g, D_, (long long)B_ * SL_ * H_);
    rms_kernel<<<(B_ * SKV_ * H_) / 8, 256>>>(kvb, qk_g, 2 * D_, (long long)B_ * SKV_ * H_);

    // 5) pack kT[b][h][d][t]
    packKT<<<dim3(SKV_ / 32, DH_ / 32, B_ * H_), dim3(32, 8)>>>(kvb, kT);

    // 6) scores = q @ kT   per (b,h): [256 x 4352 x 64]
    sgemm128<128><<<dim3(SKV_ / 128, SL_ / 128, B_ * H_), 256>>>(
        qb, D_, (long long)SL_ * D_, DH_,
        kT, SKV_, (long long)H_ * DH_ * SKV_, (long long)DH_ * SKV_,
        sb, SKV_, (long long)H_ * SL_ * SKV_, (long long)SL_ * SKV_,
        DH_, H_);

    // 7) softmax (scale + mask inside)
    softmax_kernel<<<dim3(SL_, H_, B_), 256>>>(sb, mask_x, mask_l);

    // 8) y = P @ V   per (b,h): [256 x 64 x 4352]
    sgemm128<64><<<dim3(DH_ / 64, SL_ / 128, B_ * H_), 256>>>(
        sb, SKV_, (long long)H_ * SL_ * SKV_, (long long)SL_ * SKV_,
        kvb + D_, 2 * D_, (long long)SKV_ * 2 * D_, DH_,
        yb, D_, (long long)SL_ * D_, DH_,
        SKV_, H_);

    // 9) out = y @ Wo   [1024 x 1024 x 1024]
    sgemm128<128><<<dim3(D_ / 128, (B_ * SL_) / 128, 1), 256>>>(
        yb, D_, 0, 0, Wo, D_, 0, 0, out, D_, 0, 0, D_, 1);
}

// round 3
// speedup vs baseline: 2.2460x; 2.2207x over previous
#include <cuda_runtime.h>

#define B_   4
#define SX_  4096
#define SL_  256
#define D_   1024
#define H_   16
#define DH_  64
#define SKV_ (SX_ + SL_)   // 4352

// ---------------- scratch (device globals, no allocation) ----------------
__device__ float g_kvin[(size_t)B_ * SKV_ * D_];
__device__ float g_ln  [(size_t)B_ * SL_  * D_];
__device__ float g_q   [(size_t)B_ * SL_  * D_];
__device__ float g_kv  [(size_t)B_ * SKV_ * 2 * D_];
__device__ float g_kT  [(size_t)B_ * H_ * DH_ * SKV_];
__device__ float g_s   [(size_t)B_ * H_ * SL_ * SKV_];
__device__ float g_y   [(size_t)B_ * SL_  * D_];

__device__ __forceinline__ unsigned f2tf32(float f) {
    unsigned r;
    asm("cvt.rna.tf32.f32 %0, %1;" : "=r"(r) : "f"(f));
    return r;
}

__device__ __forceinline__ void mma_tf32(
    float& c0, float& c1, float& c2, float& c3,
    unsigned a0, unsigned a1, unsigned a2, unsigned a3,
    unsigned b0, unsigned b1)
{
    asm volatile(
        "mma.sync.aligned.m16n8k8.row.col.f32.tf32.tf32.f32 "
        "{%0,%1,%2,%3}, {%4,%5,%6,%7}, {%8,%9}, {%0,%1,%2,%3};"
        : "+f"(c0), "+f"(c1), "+f"(c2), "+f"(c3)
        : "r"(a0), "r"(a1), "r"(a2), "r"(a3), "r"(b0), "r"(b1));
}

// ---------------- LayerNorm: one block per row (D=1024) ----------------
__global__ __launch_bounds__(256) void ln_kernel(
    const float* __restrict__ x, const float* __restrict__ g,
    const float* __restrict__ bta, float* __restrict__ dst1,
    float* __restrict__ dst2, int rowsPerBatch, int rowOff)
{
    int r = blockIdx.x;
    int tid = threadIdx.x;
    const float* xr = x + (size_t)r * D_;

    float v[4], s = 0.f, s2 = 0.f;
#pragma unroll
    for (int i = 0; i < 4; i++) {
        v[i] = xr[tid + i * 256];
        s += v[i];
        s2 += v[i] * v[i];
    }
#pragma unroll
    for (int o = 16; o > 0; o >>= 1) {
        s  += __shfl_xor_sync(0xffffffffu, s,  o);
        s2 += __shfl_xor_sync(0xffffffffu, s2, o);
    }
    __shared__ float ss[8], ss2[8];
    int w = tid >> 5, l = tid & 31;
    if (l == 0) { ss[w] = s; ss2[w] = s2; }
    __syncthreads();
    if (tid == 0) {
        float a = 0.f, b2 = 0.f;
#pragma unroll
        for (int i = 0; i < 8; i++) { a += ss[i]; b2 += ss2[i]; }
        float mu = a * (1.f / D_);
        ss[0]  = mu;
        ss2[0] = b2 * (1.f / D_) - mu * mu;
    }
    __syncthreads();
    float mu = ss[0];
    float inv = rsqrtf(ss2[0] + 1e-5f);

    size_t drow = ((size_t)(r / rowsPerBatch) * SKV_ + (r % rowsPerBatch) + rowOff) * D_;
#pragma unroll
    for (int i = 0; i < 4; i++) {
        int c = tid + i * 256;
        float o = (v[i] - mu) * inv * g[c] + bta[c];
        dst1[drow + c] = o;
        if (dst2) dst2[(size_t)r * D_ + c] = o;
    }
}

// ---------------- tensor-core tf32 GEMM: 128 x TN tile, K-tile 16 ----------------
// C[m][n] = sum_k A[m][k]*B[k][n]; M mult of 128, N mult of TN, K mult of 16.
// 8 warps (2 x 4); warp tile 64 x (TN/4); m16n8k8 tf32 mma; fp32 accumulate.
template<int TN>
__global__ __launch_bounds__(256) void tgemm(
    const float* __restrict__ A, int lda, long long sAb, long long sAh,
    const float* __restrict__ Bm, int ldb, long long sBb, long long sBh,
    float* __restrict__ C, int ldc, long long sCb, long long sCh,
    int K, int Hdim)
{
    constexpr int NI = TN / 32;       // 8-wide n-frags per warp
    constexpr int BS = TN + 8;        // Bs stride (==8 mod 32 -> conflict-free frag loads)
    int z = blockIdx.z;
    int bb = z / Hdim, hh = z % Hdim;
    A  += (size_t)bb * sAb + (size_t)hh * sAh;
    Bm += (size_t)bb * sBb + (size_t)hh * sBh;
    C  += (size_t)bb * sCb + (size_t)hh * sCh;

    int row0 = blockIdx.y * 128, col0 = blockIdx.x * TN;

    __shared__ unsigned As[2][16][136];   // [k][m], stride 136
    __shared__ unsigned Bs[2][16][BS];    // [k][n]

    int tid  = threadIdx.x;
    int lane = tid & 31, warp = tid >> 5;
    int wm = (warp & 1) * 64;
    int wn = (warp >> 1) * (TN / 4);
    int tig = lane & 3;                   // thread-in-group (k offset)
    int grp = lane >> 2;                  // group id (m/n offset)

    // A global: m = tid>>1, k-base = (tid&1)*8, two float4
    int am = tid >> 1, akq = (tid & 1) * 8;
    const float* Aptr = A + (size_t)(row0 + am) * lda + akq;
    // B global: k = tid>>4, n chunk
    int bk = tid >> 4;
    int bn = (TN == 128) ? (tid & 15) * 8 : (tid & 15) * 4;
    const float* Bptr = Bm + (size_t)bk * ldb + col0 + bn;

    float4 a0v = *(const float4*)Aptr;
    float4 a1v = *(const float4*)(Aptr + 4);
    float4 b0v = *(const float4*)Bptr;
    float4 b1v = make_float4(0.f, 0.f, 0.f, 0.f);
    if (TN == 128) b1v = *(const float4*)(Bptr + 4);

    float acc[4][NI][4];
#pragma unroll
    for (int i = 0; i < 4; i++)
#pragma unroll
        for (int j = 0; j < NI; j++)
#pragma unroll
            for (int t = 0; t < 4; t++) acc[i][j][t] = 0.f;

    int buf = 0;
    for (int k0 = 0; k0 < K; k0 += 16) {
        As[buf][akq + 0][am] = f2tf32(a0v.x);
        As[buf][akq + 1][am] = f2tf32(a0v.y);
        As[buf][akq + 2][am] = f2tf32(a0v.z);
        As[buf][akq + 3][am] = f2tf32(a0v.w);
        As[buf][akq + 4][am] = f2tf32(a1v.x);
        As[buf][akq + 5][am] = f2tf32(a1v.y);
        As[buf][akq + 6][am] = f2tf32(a1v.z);
        As[buf][akq + 7][am] = f2tf32(a1v.w);
        Bs[buf][bk][bn + 0] = f2tf32(b0v.x);
        Bs[buf][bk][bn + 1] = f2tf32(b0v.y);
        Bs[buf][bk][bn + 2] = f2tf32(b0v.z);
        Bs[buf][bk][bn + 3] = f2tf32(b0v.w);
        if (TN == 128) {
            Bs[buf][bk][bn + 4] = f2tf32(b1v.x);
            Bs[buf][bk][bn + 5] = f2tf32(b1v.y);
            Bs[buf][bk][bn + 6] = f2tf32(b1v.z);
            Bs[buf][bk][bn + 7] = f2tf32(b1v.w);
        }
        __syncthreads();

        if (k0 + 16 < K) {
            Aptr += 16;
            a0v = *(const float4*)Aptr;
            a1v = *(const float4*)(Aptr + 4);
            Bptr += (size_t)16 * ldb;
            b0v = *(const float4*)Bptr;
            if (TN == 128) b1v = *(const float4*)(Bptr + 4);
        }

#pragma unroll
        for (int ks = 0; ks < 2; ks++) {
            int kb = ks * 8;
            unsigned af[4][4], bf[NI][2];
#pragma unroll
            for (int mi = 0; mi < 4; mi++) {
                int r = wm + mi * 16 + grp;
                af[mi][0] = As[buf][kb + tig][r];
                af[mi][1] = As[buf][kb + tig][r + 8];
                af[mi][2] = As[buf][kb + tig + 4][r];
                af[mi][3] = As[buf][kb + tig + 4][r + 8];
            }
#pragma unroll
            for (int ni = 0; ni < NI; ni++) {
                int n = wn + ni * 8 + grp;
                bf[ni][0] = Bs[buf][kb + tig][n];
                bf[ni][1] = Bs[buf][kb + tig + 4][n];
            }
#pragma unroll
            for (int mi = 0; mi < 4; mi++)
#pragma unroll
                for (int ni = 0; ni < NI; ni++)
                    mma_tf32(acc[mi][ni][0], acc[mi][ni][1], acc[mi][ni][2], acc[mi][ni][3],
                             af[mi][0], af[mi][1], af[mi][2], af[mi][3],
                             bf[ni][0], bf[ni][1]);
        }
        buf ^= 1;
    }

#pragma unroll
    for (int mi = 0; mi < 4; mi++) {
#pragma unroll
        for (int ni = 0; ni < NI; ni++) {
            int row = row0 + wm + mi * 16 + grp;
            int col = col0 + wn + ni * 8 + tig * 2;
            *(float2*)&C[(size_t)row * ldc + col] =
                make_float2(acc[mi][ni][0], acc[mi][ni][1]);
            *(float2*)&C[(size_t)(row + 8) * ldc + col] =
                make_float2(acc[mi][ni][2], acc[mi][ni][3]);
        }
    }
}

// ---------------- per-head RMSNorm (warp per 64-wide chunk) ----------------
__global__ __launch_bounds__(256) void rms_kernel(
    float* __restrict__ p, const float* __restrict__ gamma,
    int rowStride, long long totalChunks)
{
    long long chunk = (long long)blockIdx.x * 8 + (threadIdx.x >> 5);
    if (chunk >= totalChunks) return;
    int lane = threadIdx.x & 31;
    long long row = chunk / H_;
    int h = (int)(chunk % H_);
    float* base = p + row * (size_t)rowStride + h * DH_;

    float v0 = base[lane];
    float v1 = base[lane + 32];
    float ss = v0 * v0 + v1 * v1;
#pragma unroll
    for (int o = 16; o > 0; o >>= 1) ss += __shfl_xor_sync(0xffffffffu, ss, o);
    float norm = sqrtf(ss) * 0.125f;
    float scale = 1.f / fmaxf(norm, 1e-8f);
    base[lane]      = v0 * scale * gamma[lane];
    base[lane + 32] = v1 * scale * gamma[lane + 32];
}

// ---------------- pack k -> kT[b][h][d][t] ----------------
__global__ __launch_bounds__(256) void packKT(
    const float* __restrict__ kv, float* __restrict__ kT)
{
    int z = blockIdx.z;
    int b = z / H_, h = z % H_;
    __shared__ float tile[32][33];
    int t0 = blockIdx.x * 32, d0 = blockIdx.y * 32;
    int tx = threadIdx.x, ty = threadIdx.y;
#pragma unroll
    for (int j = 0; j < 4; j++) {
        int t = t0 + ty + j * 8;
        tile[ty + j * 8][tx] = kv[((size_t)b * SKV_ + t) * (2 * D_) + h * DH_ + d0 + tx];
    }
    __syncthreads();
#pragma unroll
    for (int j = 0; j < 4; j++) {
        int d = d0 + ty + j * 8;
        kT[(((size_t)b * H_ + h) * DH_ + d) * SKV_ + t0 + tx] = tile[tx][ty + j * 8];
    }
}

// ---------------- masked softmax over score rows ----------------
__global__ __launch_bounds__(256) void softmax_kernel(
    float* __restrict__ S, const float* __restrict__ mask_x,
    const float* __restrict__ mask_l)
{
    int q = blockIdx.x, h = blockIdx.y, b = blockIdx.z;
    float* row = S + (((size_t)b * H_ + h) * SL_ + q) * SKV_;
    float mlq = mask_l[b * SL_ + q];
    int tid = threadIdx.x;
    const float NEGMIN = -3.4028234663852886e38f;

    float lv[17];
    float mx = -3.4e38f;
#pragma unroll
    for (int i = 0; i < 17; i++) {
        int t = tid + i * 256;
        float km = (t < SX_) ? mask_x[b * SX_ + t] : mask_l[b * SL_ + (t - SX_)];
        float m = km * mlq;
        float sv = row[t] * 0.125f + (1.0f - m) * NEGMIN;
        lv[i] = sv;
        mx = fmaxf(mx, sv);
    }
    __shared__ float red[8];
#pragma unroll
    for (int o = 16; o > 0; o >>= 1) mx = fmaxf(mx, __shfl_xor_sync(0xffffffffu, mx, o));
    int w = tid >> 5, l = tid & 31;
    if (l == 0) red[w] = mx;
    __syncthreads();
    if (tid == 0) {
        float a = red[0];
#pragma unroll
        for (int i = 1; i < 8; i++) a = fmaxf(a, red[i]);
        red[0] = a;
    }
    __syncthreads();
    mx = red[0];
    __syncthreads();

    float sum = 0.f;
#pragma unroll
    for (int i = 0; i < 17; i++) {
        float e = expf(lv[i] - mx);
        lv[i] = e;
        sum += e;
    }
#pragma unroll
    for (int o = 16; o > 0; o >>= 1) sum += __shfl_xor_sync(0xffffffffu, sum, o);
    if (l == 0) red[w] = sum;
    __syncthreads();
    if (tid == 0) {
        float a = 0.f;
#pragma unroll
        for (int i = 0; i < 8; i++) a += red[i];
        red[0] = a;
    }
    __syncthreads();
    float inv = 1.f / red[0];
#pragma unroll
    for (int i = 0; i < 17; i++) row[tid + i * 256] = lv[i] * inv;
}

// ---------------- launch ----------------
extern "C" void kernel_launch(void* const* d_in, const int* in_sizes, int n_in,
                              void* d_out, int out_size)
{
    const float* x       = (const float*)d_in[0];
    const float* latents = (const float*)d_in[1];
    const float* mask_x  = (const float*)d_in[2];
    const float* mask_l  = (const float*)d_in[3];
    const float* ln_x_g  = (const float*)d_in[4];
    const float* ln_x_b  = (const float*)d_in[5];
    const float* ln_l_g  = (const float*)d_in[6];
    const float* ln_l_b  = (const float*)d_in[7];
    const float* Wq      = (const float*)d_in[8];
    const float* Wkv     = (const float*)d_in[9];
    const float* qk_g    = (const float*)d_in[10];
    const float* Wo      = (const float*)d_in[11];
    float* out = (float*)d_out;

    float *kvin, *lnb, *qb, *kvb, *kT, *sb, *yb;
    cudaGetSymbolAddress((void**)&kvin, g_kvin);
    cudaGetSymbolAddress((void**)&lnb,  g_ln);
    cudaGetSymbolAddress((void**)&qb,   g_q);
    cudaGetSymbolAddress((void**)&kvb,  g_kv);
    cudaGetSymbolAddress((void**)&kT,   g_kT);
    cudaGetSymbolAddress((void**)&sb,   g_s);
    cudaGetSymbolAddress((void**)&yb,   g_y);

    // 1) LayerNorms -> kvin (concat) and lnb
    ln_kernel<<<B_ * SX_, 256>>>(x, ln_x_g, ln_x_b, kvin, nullptr, SX_, 0);
    ln_kernel<<<B_ * SL_, 256>>>(latents, ln_l_g, ln_l_b, kvin, lnb, SL_, SX_);

    // 2) q = ln @ Wq   [1024 x 1024 x 1024]
    tgemm<128><<<dim3(D_ / 128, (B_ * SL_) / 128, 1), 256>>>(
        lnb, D_, 0, 0, Wq, D_, 0, 0, qb, D_, 0, 0, D_, 1);

    // 3) kv = kvin @ Wkv   [17408 x 2048 x 1024]
    tgemm<128><<<dim3((2 * D_) / 128, (B_ * SKV_) / 128, 1), 256>>>(
        kvin, D_, 0, 0, Wkv, 2 * D_, 0, 0, kvb, 2 * D_, 0, 0, D_, 1);

    // 4) RMSNorm q and k
    rms_kernel<<<(B_ * SL_ * H_) / 8, 256>>>(qb, qk_g, D_, (long long)B_ * SL_ * H_);
    rms_kernel<<<(B_ * SKV_ * H_) / 8, 256>>>(kvb, qk_g, 2 * D_, (long long)B_ * SKV_ * H_);

    // 5) pack kT[b][h][d][t]
    packKT<<<dim3(SKV_ / 32, DH_ / 32, B_ * H_), dim3(32, 8)>>>(kvb, kT);

    // 6) scores = q @ kT   per (b,h): [256 x 4352 x 64]
    tgemm<128><<<dim3(SKV_ / 128, SL_ / 128, B_ * H_), 256>>>(
        qb, D_, (long long)SL_ * D_, DH_,
        kT, SKV_, (long long)H_ * DH_ * SKV_, (long long)DH_ * SKV_,
        sb, SKV_, (long long)H_ * SL_ * SKV_, (long long)SL_ * SKV_,
        DH_, H_);

    // 7) softmax (scale + mask inside)
    softmax_kernel<<<dim3(SL_, H_, B_), 256>>>(sb, mask_x, mask_l);

    // 8) y = P @ V   per (b,h): [256 x 64 x 4352]
    tgemm<64><<<dim3(1, SL_ / 128, B_ * H_), 256>>>(
        sb, SKV_, (long long)H_ * SL_ * SKV_, (long long)SL_ * SKV_,
        kvb + D_, 2 * D_, (long long)SKV_ * 2 * D_, DH_,
        yb, D_, (long long)SL_ * D_, DH_,
        SKV_, H_);

    // 9) out = y @ Wo   [1024 x 1024 x 1024]
    tgemm<128><<<dim3(D_ / 128, (B_ * SL_) / 128, 1), 256>>>(
        yb, D_, 0, 0, Wo, D_, 0, 0, out, D_, 0, 0, D_, 1);
}

// round 4
// speedup vs baseline: 2.8450x; 1.2667x over previous
#include <cuda_runtime.h>
#include <math.h>

#define B_   4
#define SX_  4096
#define SL_  256
#define D_   1024
#define H_   16
#define DH_  64
#define SKV_ (SX_ + SL_)   // 4352

// ---------------- scratch (device globals, no allocation) ----------------
__device__ float g_kvin[(size_t)B_ * SKV_ * D_];
__device__ float g_ln  [(size_t)B_ * SL_  * D_];
__device__ float g_q   [(size_t)B_ * SL_  * D_];
__device__ float g_kv  [(size_t)B_ * SKV_ * 2 * D_];
__device__ float g_y   [(size_t)B_ * SL_  * D_];

__device__ __forceinline__ unsigned f2tf32(float f) {
    unsigned r;
    asm("cvt.rna.tf32.f32 %0, %1;" : "=r"(r) : "f"(f));
    return r;
}

__device__ __forceinline__ void mma_tf32(
    float& c0, float& c1, float& c2, float& c3,
    unsigned a0, unsigned a1, unsigned a2, unsigned a3,
    unsigned b0, unsigned b1)
{
    asm volatile(
        "mma.sync.aligned.m16n8k8.row.col.f32.tf32.tf32.f32 "
        "{%0,%1,%2,%3}, {%4,%5,%6,%7}, {%8,%9}, {%0,%1,%2,%3};"
        : "+f"(c0), "+f"(c1), "+f"(c2), "+f"(c3)
        : "r"(a0), "r"(a1), "r"(a2), "r"(a3), "r"(b0), "r"(b1));
}

// ---------------- LayerNorm: one block per row (D=1024) ----------------
__global__ __launch_bounds__(256) void ln_kernel(
    const float* __restrict__ x, const float* __restrict__ g,
    const float* __restrict__ bta, float* __restrict__ dst1,
    float* __restrict__ dst2, int rowsPerBatch, int rowOff)
{
    int r = blockIdx.x;
    int tid = threadIdx.x;
    const float* xr = x + (size_t)r * D_;

    float v[4], s = 0.f, s2 = 0.f;
#pragma unroll
    for (int i = 0; i < 4; i++) {
        v[i] = xr[tid + i * 256];
        s += v[i];
        s2 += v[i] * v[i];
    }
#pragma unroll
    for (int o = 16; o > 0; o >>= 1) {
        s  += __shfl_xor_sync(0xffffffffu, s,  o);
        s2 += __shfl_xor_sync(0xffffffffu, s2, o);
    }
    __shared__ float ss[8], ss2[8];
    int w = tid >> 5, l = tid & 31;
    if (l == 0) { ss[w] = s; ss2[w] = s2; }
    __syncthreads();
    if (tid == 0) {
        float a = 0.f, b2 = 0.f;
#pragma unroll
        for (int i = 0; i < 8; i++) { a += ss[i]; b2 += ss2[i]; }
        float mu = a * (1.f / D_);
        ss[0]  = mu;
        ss2[0] = b2 * (1.f / D_) - mu * mu;
    }
    __syncthreads();
    float mu = ss[0];
    float inv = rsqrtf(ss2[0] + 1e-5f);

    size_t drow = ((size_t)(r / rowsPerBatch) * SKV_ + (r % rowsPerBatch) + rowOff) * D_;
#pragma unroll
    for (int i = 0; i < 4; i++) {
        int c = tid + i * 256;
        float o = (v[i] - mu) * inv * g[c] + bta[c];
        dst1[drow + c] = o;
        if (dst2) dst2[(size_t)r * D_ + c] = o;
    }
}

// ---------------- tensor-core tf32 GEMM: 128 x 128 tile, K-tile 16 ----------------
template<int TN>
__global__ __launch_bounds__(256) void tgemm(
    const float* __restrict__ A, int lda, long long sAb, long long sAh,
    const float* __restrict__ Bm, int ldb, long long sBb, long long sBh,
    float* __restrict__ C, int ldc, long long sCb, long long sCh,
    int K, int Hdim)
{
    constexpr int NI = TN / 32;
    constexpr int BS = TN + 8;
    int z = blockIdx.z;
    int bb = z / Hdim, hh = z % Hdim;
    A  += (size_t)bb * sAb + (size_t)hh * sAh;
    Bm += (size_t)bb * sBb + (size_t)hh * sBh;
    C  += (size_t)bb * sCb + (size_t)hh * sCh;

    int row0 = blockIdx.y * 128, col0 = blockIdx.x * TN;

    __shared__ unsigned As[2][16][136];
    __shared__ unsigned Bs[2][16][BS];

    int tid  = threadIdx.x;
    int lane = tid & 31, warp = tid >> 5;
    int wm = (warp & 1) * 64;
    int wn = (warp >> 1) * (TN / 4);
    int tig = lane & 3;
    int grp = lane >> 2;

    int am = tid >> 1, akq = (tid & 1) * 8;
    const float* Aptr = A + (size_t)(row0 + am) * lda + akq;
    int bk = tid >> 4;
    int bn = (TN == 128) ? (tid & 15) * 8 : (tid & 15) * 4;
    const float* Bptr = Bm + (size_t)bk * ldb + col0 + bn;

    float4 a0v = *(const float4*)Aptr;
    float4 a1v = *(const float4*)(Aptr + 4);
    float4 b0v = *(const float4*)Bptr;
    float4 b1v = make_float4(0.f, 0.f, 0.f, 0.f);
    if (TN == 128) b1v = *(const float4*)(Bptr + 4);

    float acc[4][NI][4];
#pragma unroll
    for (int i = 0; i < 4; i++)
#pragma unroll
        for (int j = 0; j < NI; j++)
#pragma unroll
            for (int t = 0; t < 4; t++) acc[i][j][t] = 0.f;

    int buf = 0;
    for (int k0 = 0; k0 < K; k0 += 16) {
        As[buf][akq + 0][am] = f2tf32(a0v.x);
        As[buf][akq + 1][am] = f2tf32(a0v.y);
        As[buf][akq + 2][am] = f2tf32(a0v.z);
        As[buf][akq + 3][am] = f2tf32(a0v.w);
        As[buf][akq + 4][am] = f2tf32(a1v.x);
        As[buf][akq + 5][am] = f2tf32(a1v.y);
        As[buf][akq + 6][am] = f2tf32(a1v.z);
        As[buf][akq + 7][am] = f2tf32(a1v.w);
        Bs[buf][bk][bn + 0] = f2tf32(b0v.x);
        Bs[buf][bk][bn + 1] = f2tf32(b0v.y);
        Bs[buf][bk][bn + 2] = f2tf32(b0v.z);
        Bs[buf][bk][bn + 3] = f2tf32(b0v.w);
        if (TN == 128) {
            Bs[buf][bk][bn + 4] = f2tf32(b1v.x);
            Bs[buf][bk][bn + 5] = f2tf32(b1v.y);
            Bs[buf][bk][bn + 6] = f2tf32(b1v.z);
            Bs[buf][bk][bn + 7] = f2tf32(b1v.w);
        }
        __syncthreads();

        if (k0 + 16 < K) {
            Aptr += 16;
            a0v = *(const float4*)Aptr;
            a1v = *(const float4*)(Aptr + 4);
            Bptr += (size_t)16 * ldb;
            b0v = *(const float4*)Bptr;
            if (TN == 128) b1v = *(const float4*)(Bptr + 4);
        }

#pragma unroll
        for (int ks = 0; ks < 2; ks++) {
            int kb = ks * 8;
            unsigned af[4][4], bf[NI][2];
#pragma unroll
            for (int mi = 0; mi < 4; mi++) {
                int r = wm + mi * 16 + grp;
                af[mi][0] = As[buf][kb + tig][r];
                af[mi][1] = As[buf][kb + tig][r + 8];
                af[mi][2] = As[buf][kb + tig + 4][r];
                af[mi][3] = As[buf][kb + tig + 4][r + 8];
            }
#pragma unroll
            for (int ni = 0; ni < NI; ni++) {
                int n = wn + ni * 8 + grp;
                bf[ni][0] = Bs[buf][kb + tig][n];
                bf[ni][1] = Bs[buf][kb + tig + 4][n];
            }
#pragma unroll
            for (int mi = 0; mi < 4; mi++)
#pragma unroll
                for (int ni = 0; ni < NI; ni++)
                    mma_tf32(acc[mi][ni][0], acc[mi][ni][1], acc[mi][ni][2], acc[mi][ni][3],
                             af[mi][0], af[mi][1], af[mi][2], af[mi][3],
                             bf[ni][0], bf[ni][1]);
        }
        buf ^= 1;
    }

#pragma unroll
    for (int mi = 0; mi < 4; mi++) {
#pragma unroll
        for (int ni = 0; ni < NI; ni++) {
            int row = row0 + wm + mi * 16 + grp;
            int col = col0 + wn + ni * 8 + tig * 2;
            *(float2*)&C[(size_t)row * ldc + col] =
                make_float2(acc[mi][ni][0], acc[mi][ni][1]);
            *(float2*)&C[(size_t)(row + 8) * ldc + col] =
                make_float2(acc[mi][ni][2], acc[mi][ni][3]);
        }
    }
}

// ---------------- per-head RMSNorm (warp per 64-wide chunk) ----------------
__global__ __launch_bounds__(256) void rms_kernel(
    float* __restrict__ p, const float* __restrict__ gamma,
    int rowStride, long long totalChunks, float outscale)
{
    long long chunk = (long long)blockIdx.x * 8 + (threadIdx.x >> 5);
    if (chunk >= totalChunks) return;
    int lane = threadIdx.x & 31;
    long long row = chunk / H_;
    int h = (int)(chunk % H_);
    float* base = p + row * (size_t)rowStride + h * DH_;

    float v0 = base[lane];
    float v1 = base[lane + 32];
    float ss = v0 * v0 + v1 * v1;
#pragma unroll
    for (int o = 16; o > 0; o >>= 1) ss += __shfl_xor_sync(0xffffffffu, ss, o);
    float norm = sqrtf(ss) * 0.125f;
    float scale = outscale / fmaxf(norm, 1e-8f);
    base[lane]      = v0 * scale * gamma[lane];
    base[lane + 32] = v1 * scale * gamma[lane + 32];
}

// ---------------- fused flash attention ----------------
// grid: (SL/128, B*H), block 256 (8 warps x 16 q-rows).
// q pre-scaled by 1/8 in rms pass. kv-tile = 64.
#define KSS 68
#define VSS 72
#define PSS 76

__global__ __launch_bounds__(256) void flash_kernel(
    const float* __restrict__ qb, const float* __restrict__ kvb,
    const float* __restrict__ mask_x, const float* __restrict__ mask_l,
    float* __restrict__ y)
{
    extern __shared__ float sm[];
    float* Ks = sm;                       // [64][68] tf32 bits
    float* Vs = Ks + 64 * KSS;            // [64][72] tf32 bits
    float* Ps = Vs + 64 * VSS;            // [128][76] Q staging / P tf32 bits
    float* Ms = Ps + 128 * PSS;           // [64] kv mask

    const float NEGMIN = -3.4028234663852886e38f;
    int tid = threadIdx.x;
    int lane = tid & 31, warp = tid >> 5;
    int grp = lane >> 2, tig = lane & 3;
    int b = blockIdx.y >> 4, h = blockIdx.y & 15;
    int q0 = blockIdx.x * 128;
    int r0 = warp * 16 + grp;

    // stage Q tile -> Ps, then extract per-thread fragments
    const float* Qg = qb + ((size_t)b * SL_ + q0) * D_ + h * DH_;
    {
        int r = tid >> 4, c4 = (tid & 15) * 4;
#pragma unroll
        for (int p = 0; p < 8; p++) {
            float4 v = *(const float4*)(Qg + (size_t)(p * 16 + r) * D_ + c4);
            *(float4*)(Ps + (p * 16 + r) * PSS + c4) = v;
        }
    }
    __syncthreads();

    unsigned qf[8][4];
#pragma unroll
    for (int c = 0; c < 8; c++) {
        qf[c][0] = f2tf32(Ps[r0 * PSS + c * 8 + tig]);
        qf[c][1] = f2tf32(Ps[(r0 + 8) * PSS + c * 8 + tig]);
        qf[c][2] = f2tf32(Ps[r0 * PSS + c * 8 + tig + 4]);
        qf[c][3] = f2tf32(Ps[(r0 + 8) * PSS + c * 8 + tig + 4]);
    }
    float mlq0 = mask_l[b * SL_ + q0 + r0];
    float mlq1 = mask_l[b * SL_ + q0 + r0 + 8];

    float m0 = -INFINITY, m1 = -INFINITY, l0 = 0.f, l1 = 0.f;
    float o[8][4];
#pragma unroll
    for (int i = 0; i < 8; i++)
#pragma unroll
        for (int j = 0; j < 4; j++) o[i][j] = 0.f;

    const float* Kg = kvb + (size_t)b * SKV_ * (2 * D_) + h * DH_;

    for (int kt = 0; kt < SKV_ / 64; kt++) {
        __syncthreads();
        {
            int r = tid >> 4, c4 = (tid & 15) * 4;
#pragma unroll
            for (int p = 0; p < 4; p++) {
                const float* src = Kg + (size_t)(kt * 64 + p * 16 + r) * (2 * D_) + c4;
                float4 kvv = *(const float4*)src;
                float4 vvv = *(const float4*)(src + D_);
                kvv.x = __uint_as_float(f2tf32(kvv.x));
                kvv.y = __uint_as_float(f2tf32(kvv.y));
                kvv.z = __uint_as_float(f2tf32(kvv.z));
                kvv.w = __uint_as_float(f2tf32(kvv.w));
                vvv.x = __uint_as_float(f2tf32(vvv.x));
                vvv.y = __uint_as_float(f2tf32(vvv.y));
                vvv.z = __uint_as_float(f2tf32(vvv.z));
                vvv.w = __uint_as_float(f2tf32(vvv.w));
                *(float4*)(Ks + (p * 16 + r) * KSS + c4) = kvv;
                *(float4*)(Vs + (p * 16 + r) * VSS + c4) = vvv;
            }
        }
        if (tid < 64) {
            int t = kt * 64 + tid;
            Ms[tid] = (t < SX_) ? mask_x[b * SX_ + t] : mask_l[b * SL_ + t - SX_];
        }
        __syncthreads();

        // S = Q K^T  (q pre-scaled)
        float s[8][4];
#pragma unroll
        for (int i = 0; i < 8; i++) { s[i][0] = s[i][1] = s[i][2] = s[i][3] = 0.f; }
#pragma unroll
        for (int c = 0; c < 8; c++) {
#pragma unroll
            for (int ni = 0; ni < 8; ni++) {
                unsigned kb0 = __float_as_uint(Ks[(ni * 8 + grp) * KSS + c * 8 + tig]);
                unsigned kb1 = __float_as_uint(Ks[(ni * 8 + grp) * KSS + c * 8 + tig + 4]);
                mma_tf32(s[ni][0], s[ni][1], s[ni][2], s[ni][3],
                         qf[c][0], qf[c][1], qf[c][2], qf[c][3], kb0, kb1);
            }
        }

        // mask + online softmax
        float mx0 = m0, mx1 = m1;
#pragma unroll
        for (int ni = 0; ni < 8; ni++) {
            float mk0 = Ms[ni * 8 + tig * 2], mk1 = Ms[ni * 8 + tig * 2 + 1];
            s[ni][0] += (1.f - mk0 * mlq0) * NEGMIN;
            s[ni][1] += (1.f - mk1 * mlq0) * NEGMIN;
            s[ni][2] += (1.f - mk0 * mlq1) * NEGMIN;
            s[ni][3] += (1.f - mk1 * mlq1) * NEGMIN;
            mx0 = fmaxf(mx0, fmaxf(s[ni][0], s[ni][1]));
            mx1 = fmaxf(mx1, fmaxf(s[ni][2], s[ni][3]));
        }
        mx0 = fmaxf(mx0, __shfl_xor_sync(0xffffffffu, mx0, 1));
        mx0 = fmaxf(mx0, __shfl_xor_sync(0xffffffffu, mx0, 2));
        mx1 = fmaxf(mx1, __shfl_xor_sync(0xffffffffu, mx1, 1));
        mx1 = fmaxf(mx1, __shfl_xor_sync(0xffffffffu, mx1, 2));
        float sc0 = expf(m0 - mx0);
        float sc1 = expf(m1 - mx1);
        m0 = mx0; m1 = mx1;
        float rs0 = 0.f, rs1 = 0.f;
#pragma unroll
        for (int ni = 0; ni < 8; ni++) {
            float p0 = expf(s[ni][0] - m0), p1 = expf(s[ni][1] - m0);
            float p2 = expf(s[ni][2] - m1), p3 = expf(s[ni][3] - m1);
            rs0 += p0 + p1; rs1 += p2 + p3;
            *(float2*)(Ps + r0 * PSS + ni * 8 + tig * 2) =
                make_float2(__uint_as_float(f2tf32(p0)), __uint_as_float(f2tf32(p1)));
            *(float2*)(Ps + (r0 + 8) * PSS + ni * 8 + tig * 2) =
                make_float2(__uint_as_float(f2tf32(p2)), __uint_as_float(f2tf32(p3)));
        }
        rs0 += __shfl_xor_sync(0xffffffffu, rs0, 1);
        rs0 += __shfl_xor_sync(0xffffffffu, rs0, 2);
        rs1 += __shfl_xor_sync(0xffffffffu, rs1, 1);
        rs1 += __shfl_xor_sync(0xffffffffu, rs1, 2);
        l0 = l0 * sc0 + rs0;
        l1 = l1 * sc1 + rs1;
#pragma unroll
        for (int ni = 0; ni < 8; ni++) {
            o[ni][0] *= sc0; o[ni][1] *= sc0;
            o[ni][2] *= sc1; o[ni][3] *= sc1;
        }
        __syncwarp();

        // O += P V
#pragma unroll
        for (int c = 0; c < 8; c++) {
            unsigned pf0 = __float_as_uint(Ps[r0 * PSS + c * 8 + tig]);
            unsigned pf1 = __float_as_uint(Ps[(r0 + 8) * PSS + c * 8 + tig]);
            unsigned pf2 = __float_as_uint(Ps[r0 * PSS + c * 8 + tig + 4]);
            unsigned pf3 = __float_as_uint(Ps[(r0 + 8) * PSS + c * 8 + tig + 4]);
#pragma unroll
            for (int ni = 0; ni < 8; ni++) {
                unsigned vb0 = __float_as_uint(Vs[(c * 8 + tig) * VSS + ni * 8 + grp]);
                unsigned vb1 = __float_as_uint(Vs[(c * 8 + tig + 4) * VSS + ni * 8 + grp]);
                mma_tf32(o[ni][0], o[ni][1], o[ni][2], o[ni][3],
                         pf0, pf1, pf2, pf3, vb0, vb1);
            }
        }
    }

    float inv0 = 1.f / l0, inv1 = 1.f / l1;
    float* yg = y + ((size_t)b * SL_ + q0 + r0) * D_ + h * DH_;
#pragma unroll
    for (int ni = 0; ni < 8; ni++) {
        *(float2*)(yg + ni * 8 + tig * 2) =
            make_float2(o[ni][0] * inv0, o[ni][1] * inv0);
        *(float2*)(yg + (size_t)8 * D_ + ni * 8 + tig * 2) =
            make_float2(o[ni][2] * inv1, o[ni][3] * inv1);
    }
}

// ---------------- launch ----------------
extern "C" void kernel_launch(void* const* d_in, const int* in_sizes, int n_in,
                              void* d_out, int out_size)
{
    const float* x       = (const float*)d_in[0];
    const float* latents = (const float*)d_in[1];
    const float* mask_x  = (const float*)d_in[2];
    const float* mask_l  = (const float*)d_in[3];
    const float* ln_x_g  = (const float*)d_in[4];
    const float* ln_x_b  = (const float*)d_in[5];
    const float* ln_l_g  = (const float*)d_in[6];
    const float* ln_l_b  = (const float*)d_in[7];
    const float* Wq      = (const float*)d_in[8];
    const float* Wkv     = (const float*)d_in[9];
    const float* qk_g    = (const float*)d_in[10];
    const float* Wo      = (const float*)d_in[11];
    float* out = (float*)d_out;

    float *kvin, *lnb, *qb, *kvb, *yb;
    cudaGetSymbolAddress((void**)&kvin, g_kvin);
    cudaGetSymbolAddress((void**)&lnb,  g_ln);
    cudaGetSymbolAddress((void**)&qb,   g_q);
    cudaGetSymbolAddress((void**)&kvb,  g_kv);
    cudaGetSymbolAddress((void**)&yb,   g_y);

    static int smem_set = 0;
    int flash_smem = (64 * KSS + 64 * VSS + 128 * PSS + 64) * 4;
    if (!smem_set) {
        cudaFuncSetAttribute(flash_kernel,
                             cudaFuncAttributeMaxDynamicSharedMemorySize, flash_smem);
        smem_set = 1;
    }

    // 1) LayerNorms -> kvin (concat) and lnb
    ln_kernel<<<B_ * SX_, 256>>>(x, ln_x_g, ln_x_b, kvin, nullptr, SX_, 0);
    ln_kernel<<<B_ * SL_, 256>>>(latents, ln_l_g, ln_l_b, kvin, lnb, SL_, SX_);

    // 2) q = ln @ Wq
    tgemm<128><<<dim3(D_ / 128, (B_ * SL_) / 128, 1), 256>>>(
        lnb, D_, 0, 0, Wq, D_, 0, 0, qb, D_, 0, 0, D_, 1);

    // 3) kv = kvin @ Wkv
    tgemm<128><<<dim3((2 * D_) / 128, (B_ * SKV_) / 128, 1), 256>>>(
        kvin, D_, 0, 0, Wkv, 2 * D_, 0, 0, kvb, 2 * D_, 0, 0, D_, 1);

    // 4) RMSNorm: q gets the 1/sqrt(DH)=0.125 score scale folded in
    rms_kernel<<<(B_ * SL_ * H_) / 8, 256>>>(qb, qk_g, D_, (long long)B_ * SL_ * H_, 0.125f);
    rms_kernel<<<(B_ * SKV_ * H_) / 8, 256>>>(kvb, qk_g, 2 * D_, (long long)B_ * SKV_ * H_, 1.0f);

    // 5) fused attention -> y
    flash_kernel<<<dim3(SL_ / 128, B_ * H_), 256, flash_smem>>>(
        qb, kvb, mask_x, mask_l, yb);

    // 6) out = y @ Wo
    tgemm<128><<<dim3(D_ / 128, (B_ * SL_) / 128, 1), 256>>>(
        yb, D_, 0, 0, Wo, D_, 0, 0, out, D_, 0, 0, D_, 1);
}